// round 1
// baseline (speedup 1.0000x reference)
#include <cuda_runtime.h>
#include <math.h>

// ---------------- problem constants ----------------
#define BSZ    4
#define TSEQ   2048
#define DMODEL 1024
#define NH     16
#define DK     64
#define MROWS  (BSZ*TSEQ)          // 8192
#define QKV_ELEMS (BSZ*NH*TSEQ*DK) // 8388608

// ---------------- scratch (static device globals; no allocs allowed) -----
__device__ float g_Q[QKV_ELEMS];
__device__ float g_K[QKV_ELEMS];
__device__ float g_V[QKV_ELEMS];
__device__ float g_att[MROWS*DMODEL];

// =========================================================================
// GEMM: C[m,n] = sum_k A[m,k] * W[n,k] + bias[n]
// A: (8192,1024) row-major, W: (1024,1024) row-major (nn.Linear weight)
// mode 0: write C row-major (m, n) -> out
// mode 1: write into (B,H,T,dk) layout: out[((b*NH+h)*TSEQ+t)*DK + c]
// Tiling: 128x128x16, 256 threads, 8x8 micro-tile, register prefetch.
// =========================================================================
__global__ __launch_bounds__(256, 2)
void gemm128_nt(const float* __restrict__ A, const float* __restrict__ W,
                const float* __restrict__ bias, float* __restrict__ out,
                int mode)
{
    __shared__ float As[16][132];
    __shared__ float Bs[16][132];
    const int K = DMODEL;

    int tid = threadIdx.x;
    int m0 = blockIdx.y * 128;
    int n0 = blockIdx.x * 128;
    int tm = tid >> 4;      // 0..15
    int tn = tid & 15;      // 0..15
    int lrow = tid >> 2;    // 0..63
    int lseg = tid & 3;     // 0..3

    const float* Ap = A + (size_t)(m0 + lrow) * K + lseg * 4;
    const float* Wp = W + (size_t)(n0 + lrow) * K + lseg * 4;

    float acc[8][8];
#pragma unroll
    for (int i = 0; i < 8; i++)
#pragma unroll
        for (int j = 0; j < 8; j++) acc[i][j] = 0.f;

    // prefetch first tile into registers
    float4 a0 = *(const float4*)(Ap);
    float4 a1 = *(const float4*)(Ap + (size_t)64 * K);
    float4 b0 = *(const float4*)(Wp);
    float4 b1 = *(const float4*)(Wp + (size_t)64 * K);

    for (int k0 = 0; k0 < K; k0 += 16) {
        // stage to shared (transposed: [k][m])
        int kc = lseg * 4;
        As[kc+0][lrow] = a0.x;  As[kc+1][lrow] = a0.y;
        As[kc+2][lrow] = a0.z;  As[kc+3][lrow] = a0.w;
        As[kc+0][lrow+64] = a1.x;  As[kc+1][lrow+64] = a1.y;
        As[kc+2][lrow+64] = a1.z;  As[kc+3][lrow+64] = a1.w;
        Bs[kc+0][lrow] = b0.x;  Bs[kc+1][lrow] = b0.y;
        Bs[kc+2][lrow] = b0.z;  Bs[kc+3][lrow] = b0.w;
        Bs[kc+0][lrow+64] = b1.x;  Bs[kc+1][lrow+64] = b1.y;
        Bs[kc+2][lrow+64] = b1.z;  Bs[kc+3][lrow+64] = b1.w;
        __syncthreads();

        if (k0 + 16 < K) {  // prefetch next tile while computing
            a0 = *(const float4*)(Ap + k0 + 16);
            a1 = *(const float4*)(Ap + (size_t)64 * K + k0 + 16);
            b0 = *(const float4*)(Wp + k0 + 16);
            b1 = *(const float4*)(Wp + (size_t)64 * K + k0 + 16);
        }

#pragma unroll
        for (int kk = 0; kk < 16; kk++) {
            float ar[8], br[8];
            *(float4*)&ar[0] = *(const float4*)&As[kk][tm * 8];
            *(float4*)&ar[4] = *(const float4*)&As[kk][tm * 8 + 4];
            *(float4*)&br[0] = *(const float4*)&Bs[kk][tn * 8];
            *(float4*)&br[4] = *(const float4*)&Bs[kk][tn * 8 + 4];
#pragma unroll
            for (int i = 0; i < 8; i++)
#pragma unroll
                for (int j = 0; j < 8; j++)
                    acc[i][j] += ar[i] * br[j];
        }
        __syncthreads();
    }

    // epilogue
    float bb[8];
    *(float4*)&bb[0] = *(const float4*)&bias[n0 + tn * 8];
    *(float4*)&bb[4] = *(const float4*)&bias[n0 + tn * 8 + 4];

    if (mode == 0) {
#pragma unroll
        for (int i = 0; i < 8; i++) {
            int m = m0 + tm * 8 + i;
            float* op = out + (size_t)m * DMODEL + n0 + tn * 8;
            float4 v0 = make_float4(acc[i][0]+bb[0], acc[i][1]+bb[1],
                                    acc[i][2]+bb[2], acc[i][3]+bb[3]);
            float4 v1 = make_float4(acc[i][4]+bb[4], acc[i][5]+bb[5],
                                    acc[i][6]+bb[6], acc[i][7]+bb[7]);
            *(float4*)op = v0;
            *(float4*)(op + 4) = v1;
        }
    } else {
        int nb = n0 + tn * 8;
        int h  = nb >> 6;          // 8-aligned block never crosses head
        int c  = nb & 63;
#pragma unroll
        for (int i = 0; i < 8; i++) {
            int m = m0 + tm * 8 + i;
            int b = m >> 11;
            int t = m & 2047;
            float* op = out + (((size_t)(b * NH + h) * TSEQ + t) * DK + c);
            float4 v0 = make_float4(acc[i][0]+bb[0], acc[i][1]+bb[1],
                                    acc[i][2]+bb[2], acc[i][3]+bb[3]);
            float4 v1 = make_float4(acc[i][4]+bb[4], acc[i][5]+bb[5],
                                    acc[i][6]+bb[6], acc[i][7]+bb[7]);
            *(float4*)op = v0;
            *(float4*)(op + 4) = v1;
        }
    }
}

// =========================================================================
// RoPE in place on g_Q and g_K. One thread per rotation pair (i, i+32).
// =========================================================================
__global__ void rope_kernel()
{
    int idx = blockIdx.x * blockDim.x + threadIdx.x;  // B*H*T*32 = 4194304
    int i  = idx & 31;
    int t  = (idx >> 5) & (TSEQ - 1);
    int bh = idx >> 16;                  // 32*2048 = 65536 per (b,h)

    float invf = powf(10000.0f, -(float)i * (1.0f / 32.0f));
    float ang  = (float)t * invf;
    float s, c;
    sincosf(ang, &s, &c);

    int base = (bh * TSEQ + t) * DK + i;
    float q1 = g_Q[base], q2 = g_Q[base + 32];
    g_Q[base]      = q1 * c - q2 * s;
    g_Q[base + 32] = q2 * c + q1 * s;
    float k1 = g_K[base], k2 = g_K[base + 32];
    g_K[base]      = k1 * c - k2 * s;
    g_K[base + 32] = k2 * c + k1 * s;
}

// =========================================================================
// Flash attention: one block per (bh, 64-query tile). 256 threads.
// Shared: Qst[d][m] (Q^T, pre-scaled), Kst[d][n] (K^T), Vs[k][d], Ss[n][m]=P^T
// Online softmax with running (m, l), O in registers (4x4 per thread).
// =========================================================================
#define ATT_PAD 68
#define ATT_SMEM_FLOATS (4*64*ATT_PAD + 4*64)
#define ATT_SMEM_BYTES  (ATT_SMEM_FLOATS*4)

__global__ __launch_bounds__(256, 2)
void attn_kernel(const unsigned char* __restrict__ mask)
{
    extern __shared__ float sh[];
    float* Qst   = sh;                    // [64][68]
    float* Kst   = sh + 64*ATT_PAD;       // [64][68]
    float* Vs    = sh + 2*64*ATT_PAD;     // [64][68]
    float* Ss    = sh + 3*64*ATT_PAD;     // [64][68]  (stores P^T: [key][query])
    float* sm_m  = sh + 4*64*ATT_PAD;
    float* sm_l  = sm_m + 64;
    float* sm_a  = sm_l + 64;
    float* sm_mk = sm_a + 64;

    int tid = threadIdx.x;
    int tm = tid >> 4;   // 0..15 (query micro-row group)
    int tn = tid & 15;   // 0..15 (col micro group)
    int bh = blockIdx.y;
    int b  = bh >> 4;
    int h  = bh & 15;
    int q0 = blockIdx.x * 64;

    const float* Qg = g_Q + ((size_t)bh * TSEQ + q0) * DK;
    const unsigned char* mk = mask + (size_t)b * TSEQ;

    int lrow = tid >> 2, lseg = tid & 3;

    // load Q tile transposed, pre-scaled by 1/sqrt(dk)
#pragma unroll
    for (int u = 0; u < 4; u++) {
        int d0 = lseg * 16 + u * 4;
        float4 q = *(const float4*)&Qg[lrow * DK + d0];
        Qst[(d0+0)*ATT_PAD + lrow] = q.x * 0.125f;
        Qst[(d0+1)*ATT_PAD + lrow] = q.y * 0.125f;
        Qst[(d0+2)*ATT_PAD + lrow] = q.z * 0.125f;
        Qst[(d0+3)*ATT_PAD + lrow] = q.w * 0.125f;
    }
    if (tid < 64) { sm_m[tid] = -1e30f; sm_l[tid] = 0.f; }

    float o[4][4];
#pragma unroll
    for (int i = 0; i < 4; i++)
#pragma unroll
        for (int j = 0; j < 4; j++) o[i][j] = 0.f;

    __syncthreads();

    for (int k0 = 0; k0 < TSEQ; k0 += 64) {
        // ---- load K (transposed) and V (natural) tiles ----
        const float* Kg = g_K + ((size_t)bh * TSEQ + k0) * DK;
        const float* Vg = g_V + ((size_t)bh * TSEQ + k0) * DK;
#pragma unroll
        for (int u = 0; u < 4; u++) {
            int d0 = lseg * 16 + u * 4;
            float4 kv = *(const float4*)&Kg[lrow * DK + d0];
            Kst[(d0+0)*ATT_PAD + lrow] = kv.x;
            Kst[(d0+1)*ATT_PAD + lrow] = kv.y;
            Kst[(d0+2)*ATT_PAD + lrow] = kv.z;
            Kst[(d0+3)*ATT_PAD + lrow] = kv.w;
            float4 vv = *(const float4*)&Vg[lrow * DK + d0];
            *(float4*)&Vs[lrow * ATT_PAD + d0] = vv;
        }
        if (tid < 64) sm_mk[tid] = mk[k0 + tid] ? -1e30f : 0.f;
        __syncthreads();

        // ---- S = (Q/8) K^T : 4x4 micro-tile per thread ----
        float s[4][4];
#pragma unroll
        for (int i = 0; i < 4; i++)
#pragma unroll
            for (int j = 0; j < 4; j++) s[i][j] = 0.f;

#pragma unroll 8
        for (int d = 0; d < DK; d++) {
            float4 a = *(const float4*)&Qst[d * ATT_PAD + tm * 4];
            float4 c = *(const float4*)&Kst[d * ATT_PAD + tn * 4];
            float av[4] = {a.x, a.y, a.z, a.w};
            float cv[4] = {c.x, c.y, c.z, c.w};
#pragma unroll
            for (int i = 0; i < 4; i++)
#pragma unroll
                for (int j = 0; j < 4; j++)
                    s[i][j] += av[i] * cv[j];
        }
        // write S transposed (Ss[n][m]) with mask applied additively
#pragma unroll
        for (int j = 0; j < 4; j++) {
            float mv = sm_mk[tn * 4 + j];
            float4 st = make_float4(s[0][j]+mv, s[1][j]+mv, s[2][j]+mv, s[3][j]+mv);
            *(float4*)&Ss[(tn * 4 + j) * ATT_PAD + tm * 4] = st;
        }
        __syncthreads();

        // ---- online softmax: one thread per query row ----
        if (tid < 64) {
            int row = tid;
            float m_old = sm_m[row];
            float l_old = sm_l[row];
            float tmax = m_old;
#pragma unroll 8
            for (int n = 0; n < 64; n++) {
                float sv = Ss[n * ATT_PAD + row];
                tmax = fmaxf(tmax, sv);
            }
            float alpha = __expf(m_old - tmax);
            float lsum = 0.f;
#pragma unroll 8
            for (int n = 0; n < 64; n++) {
                float p = __expf(Ss[n * ATT_PAD + row] - tmax);
                Ss[n * ATT_PAD + row] = p;
                lsum += p;
            }
            sm_m[row] = tmax;
            sm_l[row] = l_old * alpha + lsum;
            sm_a[row] = alpha;
        }
        __syncthreads();

        // ---- O = O*alpha + P V ----
        float al[4];
#pragma unroll
        for (int i = 0; i < 4; i++) al[i] = sm_a[tm * 4 + i];
#pragma unroll
        for (int i = 0; i < 4; i++)
#pragma unroll
            for (int j = 0; j < 4; j++) o[i][j] *= al[i];

#pragma unroll 8
        for (int k = 0; k < 64; k++) {
            float4 p = *(const float4*)&Ss[k * ATT_PAD + tm * 4];
            float4 v = *(const float4*)&Vs[k * ATT_PAD + tn * 4];
            float pv[4] = {p.x, p.y, p.z, p.w};
            float vv[4] = {v.x, v.y, v.z, v.w};
#pragma unroll
            for (int i = 0; i < 4; i++)
#pragma unroll
                for (int j = 0; j < 4; j++)
                    o[i][j] += pv[i] * vv[j];
        }
        __syncthreads();
    }

    // ---- finalize: divide by l, write to (B,T,D) layout ----
#pragma unroll
    for (int i = 0; i < 4; i++) {
        float linv = 1.f / sm_l[tm * 4 + i];
        int m = q0 + tm * 4 + i;
        float4 w = make_float4(o[i][0]*linv, o[i][1]*linv,
                               o[i][2]*linv, o[i][3]*linv);
        *(float4*)&g_att[((size_t)(b * TSEQ + m)) * DMODEL + h * DK + tn * 4] = w;
    }
}

// =========================================================================
// launch
// =========================================================================
extern "C" void kernel_launch(void* const* d_in, const int* in_sizes, int n_in,
                              void* d_out, int out_size)
{
    const float* x          = (const float*)d_in[0];
    const unsigned char* mk = (const unsigned char*)d_in[1];
    const float* Wq = (const float*)d_in[2];
    const float* bq = (const float*)d_in[3];
    const float* Wk = (const float*)d_in[4];
    const float* bk = (const float*)d_in[5];
    const float* Wv = (const float*)d_in[6];
    const float* bv = (const float*)d_in[7];
    const float* Wo = (const float*)d_in[8];
    const float* bo = (const float*)d_in[9];
    float* out = (float*)d_out;

    float *qp, *kp, *vp, *ap;
    cudaGetSymbolAddress((void**)&qp, g_Q);
    cudaGetSymbolAddress((void**)&kp, g_K);
    cudaGetSymbolAddress((void**)&vp, g_V);
    cudaGetSymbolAddress((void**)&ap, g_att);

    cudaFuncSetAttribute(attn_kernel,
                         cudaFuncAttributeMaxDynamicSharedMemorySize,
                         ATT_SMEM_BYTES);

    dim3 gemm_grid(DMODEL / 128, MROWS / 128);  // (8, 64)

    gemm128_nt<<<gemm_grid, 256>>>(x, Wq, bq, qp, 1);
    gemm128_nt<<<gemm_grid, 256>>>(x, Wk, bk, kp, 1);
    gemm128_nt<<<gemm_grid, 256>>>(x, Wv, bv, vp, 1);

    rope_kernel<<<(BSZ * NH * TSEQ * 32) / 256, 256>>>();

    dim3 attn_grid(TSEQ / 64, BSZ * NH);        // (32, 64)
    attn_kernel<<<attn_grid, 256, ATT_SMEM_BYTES>>>(mk);

    gemm128_nt<<<gemm_grid, 256>>>(ap, Wo, bo, out, 0);
}

// round 4
// speedup vs baseline: 1.3094x; 1.3094x over previous
#include <cuda_runtime.h>
#include <cuda_bf16.h>
#include <math.h>
#include <stdint.h>

// ---------------- problem constants ----------------
#define BSZ    4
#define TSEQ   2048
#define DMODEL 1024
#define NH     16
#define DK     64
#define MROWS  (BSZ*TSEQ)          // 8192
#define QKV_ELEMS (BSZ*NH*TSEQ*DK) // 8388608

// ---------------- scratch (static device globals) ----------------
__device__ float g_Q[QKV_ELEMS];
__device__ float g_K[QKV_ELEMS];
__device__ float g_V[QKV_ELEMS];
__device__ float g_att[MROWS*DMODEL];
__device__ __nv_bfloat16 g_Ahi[MROWS*DMODEL];
__device__ __nv_bfloat16 g_Alo[MROWS*DMODEL];
__device__ __nv_bfloat16 g_Wqh[DMODEL*DMODEL], g_Wql[DMODEL*DMODEL];
__device__ __nv_bfloat16 g_Wkh[DMODEL*DMODEL], g_Wkl[DMODEL*DMODEL];
__device__ __nv_bfloat16 g_Wvh[DMODEL*DMODEL], g_Wvl[DMODEL*DMODEL];
__device__ __nv_bfloat16 g_Woh[DMODEL*DMODEL], g_Wol[DMODEL*DMODEL];

// =========================================================================
// PTX helpers (sm_100 baseline only: cp.async, ldmatrix, mma.sync)
// =========================================================================
__device__ __forceinline__ uint32_t smem_u32(const void* p) {
    uint32_t a;
    asm("{ .reg .u64 t; cvta.to.shared.u64 t, %1; cvt.u32.u64 %0, t; }"
        : "=r"(a) : "l"(p));
    return a;
}
#define SW128(off) ((off) ^ (((off) >> 3) & 0x70))

__device__ __forceinline__ void cp_async16(uint32_t s, const void* g) {
    asm volatile("cp.async.cg.shared.global [%0], [%1], 16;" :: "r"(s), "l"(g));
}
__device__ __forceinline__ void cp_commit() {
    asm volatile("cp.async.commit_group;" ::: "memory");
}
template <int N> __device__ __forceinline__ void cp_wait() {
    asm volatile("cp.async.wait_group %0;" :: "n"(N) : "memory");
}

__device__ __forceinline__ void ldm_x4(uint32_t* r, uint32_t addr) {
    asm volatile("ldmatrix.sync.aligned.m8n8.x4.shared.b16 {%0,%1,%2,%3}, [%4];"
        : "=r"(r[0]), "=r"(r[1]), "=r"(r[2]), "=r"(r[3]) : "r"(addr));
}

__device__ __forceinline__ void mma16816(float* c, const uint32_t* a,
                                         uint32_t b0, uint32_t b1) {
    asm volatile(
        "mma.sync.aligned.m16n8k16.row.col.f32.bf16.bf16.f32 "
        "{%0,%1,%2,%3}, {%4,%5,%6,%7}, {%8,%9}, {%0,%1,%2,%3};"
        : "+f"(c[0]), "+f"(c[1]), "+f"(c[2]), "+f"(c[3])
        : "r"(a[0]), "r"(a[1]), "r"(a[2]), "r"(a[3]), "r"(b0), "r"(b1));
}

// =========================================================================
// fp32 -> (bf16 hi, bf16 lo) split
// =========================================================================
__global__ void split_kernel(const float* __restrict__ src,
                             __nv_bfloat16* __restrict__ hi,
                             __nv_bfloat16* __restrict__ lo, int n)
{
    int i = (blockIdx.x * blockDim.x + threadIdx.x) * 4;
    if (i >= n) return;
    float4 v = *(const float4*)(src + i);
    __nv_bfloat16 h0 = __float2bfloat16(v.x);
    __nv_bfloat16 h1 = __float2bfloat16(v.y);
    __nv_bfloat16 h2 = __float2bfloat16(v.z);
    __nv_bfloat16 h3 = __float2bfloat16(v.w);
    __nv_bfloat16 l0 = __float2bfloat16(v.x - __bfloat162float(h0));
    __nv_bfloat16 l1 = __float2bfloat16(v.y - __bfloat162float(h1));
    __nv_bfloat16 l2 = __float2bfloat16(v.z - __bfloat162float(h2));
    __nv_bfloat16 l3 = __float2bfloat16(v.w - __bfloat162float(h3));
    *(__nv_bfloat162*)(hi + i)     = __halves2bfloat162(h0, h1);
    *(__nv_bfloat162*)(hi + i + 2) = __halves2bfloat162(h2, h3);
    *(__nv_bfloat162*)(lo + i)     = __halves2bfloat162(l0, l1);
    *(__nv_bfloat162*)(lo + i + 2) = __halves2bfloat162(l2, l3);
}

// =========================================================================
// HMMA bf16x3 GEMM: C[m,n] = sum_k A[m,k]*B[n,k] + bias[n]
// CTA 128x128, K-chunk 64, 8 warps (4m x 2n), warp tile 32x64.
// Stage layout (per stage 64KB): Ah | Al | Bh | Bl, each 128 rows x 128B SW128.
// mode 0: row-major out; mode 1: (B,H,T,dk) scatter.
// =========================================================================
#define KCH 64
#define NKB (DMODEL / KCH)        // 16
#define TILE_BYTES 16384          // 128 rows * 128B
#define STG_SZ (4 * TILE_BYTES)   // 65536
#define GEMM_SMEM (2 * STG_SZ)    // 131072

__global__ __launch_bounds__(256, 1)
void gemm_hmma(const __nv_bfloat16* __restrict__ Ah, const __nv_bfloat16* __restrict__ Al,
               const __nv_bfloat16* __restrict__ Bh, const __nv_bfloat16* __restrict__ Bl,
               const float* __restrict__ bias, float* __restrict__ out, int mode)
{
    extern __shared__ char smem[];
    uint32_t sb = smem_u32(smem);
    int tid = threadIdx.x, lane = tid & 31, wid = tid >> 5;
    int wm = wid & 3, wn = wid >> 2;       // warp grid 4(m) x 2(n)
    int n0 = blockIdx.x * 128;
    int m0 = blockIdx.y * 128;

    float acc[2][8][4];
#pragma unroll
    for (int i = 0; i < 2; i++)
#pragma unroll
        for (int j = 0; j < 8; j++)
#pragma unroll
            for (int r = 0; r < 4; r++) acc[i][j][r] = 0.f;

    // ---- producer: fill stage s with K-chunk kb ----
    auto load_stage = [&](int s, int kb) {
        uint32_t st = sb + s * STG_SZ;
        const __nv_bfloat16* pa_h = Ah + (size_t)m0 * DMODEL + kb * KCH;
        const __nv_bfloat16* pa_l = Al + (size_t)m0 * DMODEL + kb * KCH;
        const __nv_bfloat16* pb_h = Bh + (size_t)n0 * DMODEL + kb * KCH;
        const __nv_bfloat16* pb_l = Bl + (size_t)n0 * DMODEL + kb * KCH;
#pragma unroll
        for (int i = 0; i < 4; i++) {        // 1024 16B segs per tile
            int seg = tid + i * 256;
            int r = seg >> 3, c = seg & 7;
            uint32_t sw = SW128((uint32_t)(r * 128 + c * 16));
            const size_t go = (size_t)r * DMODEL + c * 8;
            cp_async16(st + sw,                  pa_h + go);
            cp_async16(st + TILE_BYTES + sw,     pa_l + go);
            cp_async16(st + 2*TILE_BYTES + sw,   pb_h + go);
            cp_async16(st + 3*TILE_BYTES + sw,   pb_l + go);
        }
        cp_commit();
    };

    load_stage(0, 0);

    // per-lane ldmatrix row/chunk decomposition (shared by A and B):
    // lane -> row_in_16 = lane & 15, k-half = lane >> 4
    int rlane = lane & 15;
    int kc    = lane >> 4;

    for (int kb = 0; kb < NKB; kb++) {
        int s = kb & 1;
        if (kb + 1 < NKB) { load_stage(s ^ 1, kb + 1); cp_wait<1>(); }
        else              { cp_wait<0>(); }
        __syncthreads();

        uint32_t stA  = sb + s * STG_SZ;
        uint32_t stAl = stA + TILE_BYTES;
        uint32_t stB  = stA + 2 * TILE_BYTES;
        uint32_t stBl = stA + 3 * TILE_BYTES;

#pragma unroll
        for (int ks = 0; ks < 4; ks++) {           // 4 x k16 per chunk
            int koff = (ks * 2 + kc) * 16;         // 16B chunk within row
            uint32_t a_h[2][4], a_l[2][4];
#pragma unroll
            for (int i = 0; i < 2; i++) {
                uint32_t off = SW128((uint32_t)((wm*32 + i*16 + rlane) * 128 + koff));
                ldm_x4(a_h[i], stA  + off);
                ldm_x4(a_l[i], stAl + off);
            }
            uint32_t b_h[8][2], b_l[8][2];
#pragma unroll
            for (int jj = 0; jj < 4; jj++) {       // each x4 covers two n8 tiles
                uint32_t off = SW128((uint32_t)((wn*64 + jj*16 + rlane) * 128 + koff));
                uint32_t r[4];
                ldm_x4(r, stB + off);
                b_h[2*jj][0] = r[0]; b_h[2*jj+1][0] = r[1];
                b_h[2*jj][1] = r[2]; b_h[2*jj+1][1] = r[3];
                ldm_x4(r, stBl + off);
                b_l[2*jj][0] = r[0]; b_l[2*jj+1][0] = r[1];
                b_l[2*jj][1] = r[2]; b_l[2*jj+1][1] = r[3];
            }
#pragma unroll
            for (int i = 0; i < 2; i++)
#pragma unroll
                for (int j = 0; j < 8; j++) {
                    mma16816(acc[i][j], a_h[i], b_h[j][0], b_h[j][1]);
                    mma16816(acc[i][j], a_h[i], b_l[j][0], b_l[j][1]);
                    mma16816(acc[i][j], a_l[i], b_h[j][0], b_h[j][1]);
                }
        }
        __syncthreads();
    }

    // ---- epilogue ----
    int crow = lane >> 2;            // 0..7
    int ccol = (lane & 3) * 2;       // 0,2,4,6
    if (mode == 0) {
#pragma unroll
        for (int i = 0; i < 2; i++) {
            int r0 = m0 + wm*32 + i*16 + crow;
#pragma unroll
            for (int j = 0; j < 8; j++) {
                int n = n0 + wn*64 + j*8 + ccol;
                float b0 = __ldg(bias + n), b1 = __ldg(bias + n + 1);
                *(float2*)(out + (size_t)r0 * DMODEL + n) =
                    make_float2(acc[i][j][0] + b0, acc[i][j][1] + b1);
                *(float2*)(out + (size_t)(r0 + 8) * DMODEL + n) =
                    make_float2(acc[i][j][2] + b0, acc[i][j][3] + b1);
            }
        }
    } else {
#pragma unroll
        for (int i = 0; i < 2; i++) {
            int r0 = m0 + wm*32 + i*16 + crow;
            int b_ = r0 >> 11, t0 = r0 & (TSEQ - 1);
#pragma unroll
            for (int j = 0; j < 8; j++) {
                int n = n0 + wn*64 + j*8 + ccol;
                int h = n >> 6, c = n & 63;
                float b0 = __ldg(bias + n), b1 = __ldg(bias + n + 1);
                size_t base = ((size_t)(b_ * NH + h) * TSEQ);
                *(float2*)(out + (base + t0) * DK + c) =
                    make_float2(acc[i][j][0] + b0, acc[i][j][1] + b1);
                *(float2*)(out + (base + t0 + 8) * DK + c) =
                    make_float2(acc[i][j][2] + b0, acc[i][j][3] + b1);
            }
        }
    }
}

// =========================================================================
// RoPE in place on g_Q and g_K.
// =========================================================================
__global__ void rope_kernel()
{
    int idx = blockIdx.x * blockDim.x + threadIdx.x;
    int i  = idx & 31;
    int t  = (idx >> 5) & (TSEQ - 1);
    int bh = idx >> 16;

    float invf = exp2f(-(float)i * (0.031250f * 13.287712379549449f));
    float ang  = (float)t * invf;
    float s, c;
    sincosf(ang, &s, &c);

    int base = (bh * TSEQ + t) * DK + i;
    float q1 = g_Q[base], q2 = g_Q[base + 32];
    g_Q[base]      = q1 * c - q2 * s;
    g_Q[base + 32] = q2 * c + q1 * s;
    float k1 = g_K[base], k2 = g_K[base + 32];
    g_K[base]      = k1 * c - k2 * s;
    g_K[base + 32] = k2 * c + k1 * s;
}

// =========================================================================
// SIMT flash attention (unchanged from R1; tensorize next round).
// =========================================================================
#define ATT_PAD 68
#define ATT_SMEM_FLOATS (4*64*ATT_PAD + 4*64)
#define ATT_SMEM_BYTES  (ATT_SMEM_FLOATS*4)

__global__ __launch_bounds__(256, 2)
void attn_kernel(const unsigned char* __restrict__ mask)
{
    extern __shared__ float sh[];
    float* Qst   = sh;
    float* Kst   = sh + 64*ATT_PAD;
    float* Vs    = sh + 2*64*ATT_PAD;
    float* Ss    = sh + 3*64*ATT_PAD;
    float* sm_m  = sh + 4*64*ATT_PAD;
    float* sm_l  = sm_m + 64;
    float* sm_a  = sm_l + 64;
    float* sm_mk = sm_a + 64;

    int tid = threadIdx.x;
    int tm = tid >> 4;
    int tn = tid & 15;
    int bh = blockIdx.y;
    int b  = bh >> 4;
    int h  = bh & 15;
    int q0 = blockIdx.x * 64;

    const float* Qg = g_Q + ((size_t)bh * TSEQ + q0) * DK;
    const unsigned char* mk = mask + (size_t)b * TSEQ;

    int lrow = tid >> 2, lseg = tid & 3;

#pragma unroll
    for (int u = 0; u < 4; u++) {
        int d0 = lseg * 16 + u * 4;
        float4 q = *(const float4*)&Qg[lrow * DK + d0];
        Qst[(d0+0)*ATT_PAD + lrow] = q.x * 0.125f;
        Qst[(d0+1)*ATT_PAD + lrow] = q.y * 0.125f;
        Qst[(d0+2)*ATT_PAD + lrow] = q.z * 0.125f;
        Qst[(d0+3)*ATT_PAD + lrow] = q.w * 0.125f;
    }
    if (tid < 64) { sm_m[tid] = -1e30f; sm_l[tid] = 0.f; }

    float o[4][4];
#pragma unroll
    for (int i = 0; i < 4; i++)
#pragma unroll
        for (int j = 0; j < 4; j++) o[i][j] = 0.f;

    __syncthreads();

    for (int k0 = 0; k0 < TSEQ; k0 += 64) {
        const float* Kg = g_K + ((size_t)bh * TSEQ + k0) * DK;
        const float* Vg = g_V + ((size_t)bh * TSEQ + k0) * DK;
#pragma unroll
        for (int u = 0; u < 4; u++) {
            int d0 = lseg * 16 + u * 4;
            float4 kv = *(const float4*)&Kg[lrow * DK + d0];
            Kst[(d0+0)*ATT_PAD + lrow] = kv.x;
            Kst[(d0+1)*ATT_PAD + lrow] = kv.y;
            Kst[(d0+2)*ATT_PAD + lrow] = kv.z;
            Kst[(d0+3)*ATT_PAD + lrow] = kv.w;
            float4 vv = *(const float4*)&Vg[lrow * DK + d0];
            *(float4*)&Vs[lrow * ATT_PAD + d0] = vv;
        }
        if (tid < 64) sm_mk[tid] = mk[k0 + tid] ? -1e30f : 0.f;
        __syncthreads();

        float s[4][4];
#pragma unroll
        for (int i = 0; i < 4; i++)
#pragma unroll
            for (int j = 0; j < 4; j++) s[i][j] = 0.f;

#pragma unroll 8
        for (int d = 0; d < DK; d++) {
            float4 a = *(const float4*)&Qst[d * ATT_PAD + tm * 4];
            float4 c = *(const float4*)&Kst[d * ATT_PAD + tn * 4];
            float av[4] = {a.x, a.y, a.z, a.w};
            float cv[4] = {c.x, c.y, c.z, c.w};
#pragma unroll
            for (int i = 0; i < 4; i++)
#pragma unroll
                for (int j = 0; j < 4; j++)
                    s[i][j] += av[i] * cv[j];
        }
#pragma unroll
        for (int j = 0; j < 4; j++) {
            float mv = sm_mk[tn * 4 + j];
            float4 st = make_float4(s[0][j]+mv, s[1][j]+mv, s[2][j]+mv, s[3][j]+mv);
            *(float4*)&Ss[(tn * 4 + j) * ATT_PAD + tm * 4] = st;
        }
        __syncthreads();

        if (tid < 64) {
            int row = tid;
            float m_old = sm_m[row];
            float l_old = sm_l[row];
            float tmax = m_old;
#pragma unroll 8
            for (int n = 0; n < 64; n++) {
                float sv = Ss[n * ATT_PAD + row];
                tmax = fmaxf(tmax, sv);
            }
            float alpha = __expf(m_old - tmax);
            float lsum = 0.f;
#pragma unroll 8
            for (int n = 0; n < 64; n++) {
                float p = __expf(Ss[n * ATT_PAD + row] - tmax);
                Ss[n * ATT_PAD + row] = p;
                lsum += p;
            }
            sm_m[row] = tmax;
            sm_l[row] = l_old * alpha + lsum;
            sm_a[row] = alpha;
        }
        __syncthreads();

        float al[4];
#pragma unroll
        for (int i = 0; i < 4; i++) al[i] = sm_a[tm * 4 + i];
#pragma unroll
        for (int i = 0; i < 4; i++)
#pragma unroll
            for (int j = 0; j < 4; j++) o[i][j] *= al[i];

#pragma unroll 8
        for (int k = 0; k < 64; k++) {
            float4 p = *(const float4*)&Ss[k * ATT_PAD + tm * 4];
            float4 v = *(const float4*)&Vs[k * ATT_PAD + tn * 4];
            float pv[4] = {p.x, p.y, p.z, p.w};
            float vv[4] = {v.x, v.y, v.z, v.w};
#pragma unroll
            for (int i = 0; i < 4; i++)
#pragma unroll
                for (int j = 0; j < 4; j++)
                    o[i][j] += pv[i] * vv[j];
        }
        __syncthreads();
    }

#pragma unroll
    for (int i = 0; i < 4; i++) {
        float linv = 1.f / sm_l[tm * 4 + i];
        int m = q0 + tm * 4 + i;
        float4 w = make_float4(o[i][0]*linv, o[i][1]*linv,
                               o[i][2]*linv, o[i][3]*linv);
        *(float4*)&g_att[((size_t)(b * TSEQ + m)) * DMODEL + h * DK + tn * 4] = w;
    }
}

// =========================================================================
// launch
// =========================================================================
extern "C" void kernel_launch(void* const* d_in, const int* in_sizes, int n_in,
                              void* d_out, int out_size)
{
    const float* x          = (const float*)d_in[0];
    const unsigned char* mk = (const unsigned char*)d_in[1];
    const float* Wq = (const float*)d_in[2];
    const float* bq = (const float*)d_in[3];
    const float* Wk = (const float*)d_in[4];
    const float* bk = (const float*)d_in[5];
    const float* Wv = (const float*)d_in[6];
    const float* bv = (const float*)d_in[7];
    const float* Wo = (const float*)d_in[8];
    const float* bo = (const float*)d_in[9];
    float* out = (float*)d_out;

    float *qp, *kp, *vp, *ap;
    __nv_bfloat16 *ah, *al, *wqh, *wql, *wkh, *wkl, *wvh, *wvl, *woh, *wol;
    cudaGetSymbolAddress((void**)&qp, g_Q);
    cudaGetSymbolAddress((void**)&kp, g_K);
    cudaGetSymbolAddress((void**)&vp, g_V);
    cudaGetSymbolAddress((void**)&ap, g_att);
    cudaGetSymbolAddress((void**)&ah, g_Ahi);
    cudaGetSymbolAddress((void**)&al, g_Alo);
    cudaGetSymbolAddress((void**)&wqh, g_Wqh);  cudaGetSymbolAddress((void**)&wql, g_Wql);
    cudaGetSymbolAddress((void**)&wkh, g_Wkh);  cudaGetSymbolAddress((void**)&wkl, g_Wkl);
    cudaGetSymbolAddress((void**)&wvh, g_Wvh);  cudaGetSymbolAddress((void**)&wvl, g_Wvl);
    cudaGetSymbolAddress((void**)&woh, g_Woh);  cudaGetSymbolAddress((void**)&wol, g_Wol);

    cudaFuncSetAttribute(gemm_hmma, cudaFuncAttributeMaxDynamicSharedMemorySize, GEMM_SMEM);
    cudaFuncSetAttribute(attn_kernel, cudaFuncAttributeMaxDynamicSharedMemorySize, ATT_SMEM_BYTES);

    const int NW = DMODEL * DMODEL;   // 1048576
    const int NX = MROWS * DMODEL;    // 8388608

    split_kernel<<<NX / 1024, 256>>>(x, ah, al, NX);
    split_kernel<<<NW / 1024, 256>>>(Wq, wqh, wql, NW);
    split_kernel<<<NW / 1024, 256>>>(Wk, wkh, wkl, NW);
    split_kernel<<<NW / 1024, 256>>>(Wv, wvh, wvl, NW);
    split_kernel<<<NW / 1024, 256>>>(Wo, woh, wol, NW);

    dim3 gg(DMODEL / 128, MROWS / 128);   // (8, 64)
    gemm_hmma<<<gg, 256, GEMM_SMEM>>>(ah, al, wqh, wql, bq, qp, 1);
    gemm_hmma<<<gg, 256, GEMM_SMEM>>>(ah, al, wkh, wkl, bk, kp, 1);
    gemm_hmma<<<gg, 256, GEMM_SMEM>>>(ah, al, wvh, wvl, bv, vp, 1);

    rope_kernel<<<(BSZ * NH * TSEQ * 32) / 256, 256>>>();

    dim3 attn_grid(TSEQ / 64, BSZ * NH);
    attn_kernel<<<attn_grid, 256, ATT_SMEM_BYTES>>>(mk);

    split_kernel<<<NX / 1024, 256>>>(ap, ah, al, NX);
    gemm_hmma<<<gg, 256, GEMM_SMEM>>>(ah, al, woh, wol, bo, out, 0);
}

// round 6
// speedup vs baseline: 3.0909x; 2.3605x over previous
#include <cuda_runtime.h>
#include <cuda_bf16.h>
#include <math.h>
#include <stdint.h>

// ---------------- problem constants ----------------
#define BSZ    4
#define TSEQ   2048
#define DMODEL 1024
#define NH     16
#define DK     64
#define MROWS  (BSZ*TSEQ)          // 8192
#define QKV_ELEMS (BSZ*NH*TSEQ*DK) // 8388608

// ---------------- scratch (static device globals) ----------------
__device__ float g_Q[QKV_ELEMS];
__device__ float g_K[QKV_ELEMS];
__device__ float g_att[MROWS*DMODEL];      // (kept for layout compat; unused)
__device__ __nv_bfloat16 g_Ahi[MROWS*DMODEL];
__device__ __nv_bfloat16 g_Alo[MROWS*DMODEL];
__device__ __nv_bfloat16 g_Qh[QKV_ELEMS], g_Ql[QKV_ELEMS];
__device__ __nv_bfloat16 g_Kh[QKV_ELEMS], g_Kl[QKV_ELEMS];
__device__ __nv_bfloat16 g_Vh[QKV_ELEMS], g_Vl[QKV_ELEMS];
__device__ __nv_bfloat16 g_Wqh[DMODEL*DMODEL], g_Wql[DMODEL*DMODEL];
__device__ __nv_bfloat16 g_Wkh[DMODEL*DMODEL], g_Wkl[DMODEL*DMODEL];
__device__ __nv_bfloat16 g_Wvh[DMODEL*DMODEL], g_Wvl[DMODEL*DMODEL];
__device__ __nv_bfloat16 g_Woh[DMODEL*DMODEL], g_Wol[DMODEL*DMODEL];

// =========================================================================
// PTX helpers (sm_100 baseline: cp.async, ldmatrix, mma.sync)
// =========================================================================
__device__ __forceinline__ uint32_t smem_u32(const void* p) {
    uint32_t a;
    asm("{ .reg .u64 t; cvta.to.shared.u64 t, %1; cvt.u32.u64 %0, t; }"
        : "=r"(a) : "l"(p));
    return a;
}
#define SW128(off) ((off) ^ (((off) >> 3) & 0x70))

__device__ __forceinline__ void cp_async16(uint32_t s, const void* g) {
    asm volatile("cp.async.cg.shared.global [%0], [%1], 16;" :: "r"(s), "l"(g));
}
__device__ __forceinline__ void cp_commit() {
    asm volatile("cp.async.commit_group;" ::: "memory");
}
template <int N> __device__ __forceinline__ void cp_wait() {
    asm volatile("cp.async.wait_group %0;" :: "n"(N) : "memory");
}

__device__ __forceinline__ void ldm_x4(uint32_t* r, uint32_t addr) {
    asm volatile("ldmatrix.sync.aligned.m8n8.x4.shared.b16 {%0,%1,%2,%3}, [%4];"
        : "=r"(r[0]), "=r"(r[1]), "=r"(r[2]), "=r"(r[3]) : "r"(addr));
}
__device__ __forceinline__ void ldm_x4_t(uint32_t* r, uint32_t addr) {
    asm volatile("ldmatrix.sync.aligned.m8n8.x4.trans.shared.b16 {%0,%1,%2,%3}, [%4];"
        : "=r"(r[0]), "=r"(r[1]), "=r"(r[2]), "=r"(r[3]) : "r"(addr));
}

__device__ __forceinline__ void mma16816(float* c, const uint32_t* a,
                                         uint32_t b0, uint32_t b1) {
    asm volatile(
        "mma.sync.aligned.m16n8k16.row.col.f32.bf16.bf16.f32 "
        "{%0,%1,%2,%3}, {%4,%5,%6,%7}, {%8,%9}, {%0,%1,%2,%3};"
        : "+f"(c[0]), "+f"(c[1]), "+f"(c[2]), "+f"(c[3])
        : "r"(a[0]), "r"(a[1]), "r"(a[2]), "r"(a[3]), "r"(b0), "r"(b1));
}

// pack two fp32 into bf16x2 (first arg in low half)
__device__ __forceinline__ uint32_t packbf(float lo, float hi) {
    uint32_t r;
    asm("cvt.rn.bf16x2.f32 %0, %1, %2;" : "=r"(r) : "f"(hi), "f"(lo));
    return r;
}

// split one fp32 into bf16 hi + bf16 lo
__device__ __forceinline__ void split1(float v, __nv_bfloat16& h, __nv_bfloat16& l) {
    h = __float2bfloat16(v);
    l = __float2bfloat16(v - __bfloat162float(h));
}

// =========================================================================
// fp32 -> (bf16 hi, bf16 lo) split
// =========================================================================
__global__ void split_kernel(const float* __restrict__ src,
                             __nv_bfloat16* __restrict__ hi,
                             __nv_bfloat16* __restrict__ lo, int n)
{
    int i = (blockIdx.x * blockDim.x + threadIdx.x) * 4;
    if (i >= n) return;
    float4 v = *(const float4*)(src + i);
    __nv_bfloat16 h0, h1, h2, h3, l0, l1, l2, l3;
    split1(v.x, h0, l0); split1(v.y, h1, l1);
    split1(v.z, h2, l2); split1(v.w, h3, l3);
    *(__nv_bfloat162*)(hi + i)     = __halves2bfloat162(h0, h1);
    *(__nv_bfloat162*)(hi + i + 2) = __halves2bfloat162(h2, h3);
    *(__nv_bfloat162*)(lo + i)     = __halves2bfloat162(l0, l1);
    *(__nv_bfloat162*)(lo + i + 2) = __halves2bfloat162(l2, l3);
}

// =========================================================================
// HMMA bf16x3 GEMM: C = A*W^T + bias
// mode 0: row-major fp32 out
// mode 1: (B,H,T,dk) fp32 scatter
// mode 2: (B,H,T,dk) bf16 hi/lo split scatter (outh/outl)
// =========================================================================
#define KCH 64
#define NKB (DMODEL / KCH)        // 16
#define TILE_BYTES 16384          // 128 rows * 128B
#define STG_SZ (4 * TILE_BYTES)   // 65536
#define GEMM_SMEM (2 * STG_SZ)    // 131072

__global__ __launch_bounds__(256, 1)
void gemm_hmma(const __nv_bfloat16* __restrict__ Ah, const __nv_bfloat16* __restrict__ Al,
               const __nv_bfloat16* __restrict__ Bh, const __nv_bfloat16* __restrict__ Bl,
               const float* __restrict__ bias, float* __restrict__ out,
               __nv_bfloat16* __restrict__ outh, __nv_bfloat16* __restrict__ outl,
               int mode)
{
    extern __shared__ char smem[];
    uint32_t sb = smem_u32(smem);
    int tid = threadIdx.x, lane = tid & 31, wid = tid >> 5;
    int wm = wid & 3, wn = wid >> 2;
    int n0 = blockIdx.x * 128;
    int m0 = blockIdx.y * 128;

    float acc[2][8][4];
#pragma unroll
    for (int i = 0; i < 2; i++)
#pragma unroll
        for (int j = 0; j < 8; j++)
#pragma unroll
            for (int r = 0; r < 4; r++) acc[i][j][r] = 0.f;

    auto load_stage = [&](int s, int kb) {
        uint32_t st = sb + s * STG_SZ;
        const __nv_bfloat16* pa_h = Ah + (size_t)m0 * DMODEL + kb * KCH;
        const __nv_bfloat16* pa_l = Al + (size_t)m0 * DMODEL + kb * KCH;
        const __nv_bfloat16* pb_h = Bh + (size_t)n0 * DMODEL + kb * KCH;
        const __nv_bfloat16* pb_l = Bl + (size_t)n0 * DMODEL + kb * KCH;
#pragma unroll
        for (int i = 0; i < 4; i++) {
            int seg = tid + i * 256;
            int r = seg >> 3, c = seg & 7;
            uint32_t sw = SW128((uint32_t)(r * 128 + c * 16));
            const size_t go = (size_t)r * DMODEL + c * 8;
            cp_async16(st + sw,                  pa_h + go);
            cp_async16(st + TILE_BYTES + sw,     pa_l + go);
            cp_async16(st + 2*TILE_BYTES + sw,   pb_h + go);
            cp_async16(st + 3*TILE_BYTES + sw,   pb_l + go);
        }
        cp_commit();
    };

    load_stage(0, 0);

    int rlane = lane & 15;
    int kc    = lane >> 4;

    for (int kb = 0; kb < NKB; kb++) {
        int s = kb & 1;
        if (kb + 1 < NKB) { load_stage(s ^ 1, kb + 1); cp_wait<1>(); }
        else              { cp_wait<0>(); }
        __syncthreads();

        uint32_t stA  = sb + s * STG_SZ;
        uint32_t stAl = stA + TILE_BYTES;
        uint32_t stB  = stA + 2 * TILE_BYTES;
        uint32_t stBl = stA + 3 * TILE_BYTES;

#pragma unroll
        for (int ks = 0; ks < 4; ks++) {
            int koff = (ks * 2 + kc) * 16;
            uint32_t a_h[2][4], a_l[2][4];
#pragma unroll
            for (int i = 0; i < 2; i++) {
                uint32_t off = SW128((uint32_t)((wm*32 + i*16 + rlane) * 128 + koff));
                ldm_x4(a_h[i], stA  + off);
                ldm_x4(a_l[i], stAl + off);
            }
            uint32_t b_h[8][2], b_l[8][2];
#pragma unroll
            for (int jj = 0; jj < 4; jj++) {
                uint32_t off = SW128((uint32_t)((wn*64 + jj*16 + rlane) * 128 + koff));
                uint32_t r[4];
                ldm_x4(r, stB + off);
                b_h[2*jj][0] = r[0]; b_h[2*jj+1][0] = r[1];
                b_h[2*jj][1] = r[2]; b_h[2*jj+1][1] = r[3];
                ldm_x4(r, stBl + off);
                b_l[2*jj][0] = r[0]; b_l[2*jj+1][0] = r[1];
                b_l[2*jj][1] = r[2]; b_l[2*jj+1][1] = r[3];
            }
#pragma unroll
            for (int i = 0; i < 2; i++)
#pragma unroll
                for (int j = 0; j < 8; j++) {
                    mma16816(acc[i][j], a_h[i], b_h[j][0], b_h[j][1]);
                    mma16816(acc[i][j], a_h[i], b_l[j][0], b_l[j][1]);
                    mma16816(acc[i][j], a_l[i], b_h[j][0], b_h[j][1]);
                }
        }
        __syncthreads();
    }

    int crow = lane >> 2;
    int ccol = (lane & 3) * 2;
    if (mode == 0) {
#pragma unroll
        for (int i = 0; i < 2; i++) {
            int r0 = m0 + wm*32 + i*16 + crow;
#pragma unroll
            for (int j = 0; j < 8; j++) {
                int n = n0 + wn*64 + j*8 + ccol;
                float b0 = __ldg(bias + n), b1 = __ldg(bias + n + 1);
                *(float2*)(out + (size_t)r0 * DMODEL + n) =
                    make_float2(acc[i][j][0] + b0, acc[i][j][1] + b1);
                *(float2*)(out + (size_t)(r0 + 8) * DMODEL + n) =
                    make_float2(acc[i][j][2] + b0, acc[i][j][3] + b1);
            }
        }
    } else if (mode == 1) {
#pragma unroll
        for (int i = 0; i < 2; i++) {
            int r0 = m0 + wm*32 + i*16 + crow;
            int b_ = r0 >> 11, t0 = r0 & (TSEQ - 1);
#pragma unroll
            for (int j = 0; j < 8; j++) {
                int n = n0 + wn*64 + j*8 + ccol;
                int h = n >> 6, c = n & 63;
                float b0 = __ldg(bias + n), b1 = __ldg(bias + n + 1);
                size_t base = ((size_t)(b_ * NH + h) * TSEQ);
                *(float2*)(out + (base + t0) * DK + c) =
                    make_float2(acc[i][j][0] + b0, acc[i][j][1] + b1);
                *(float2*)(out + (base + t0 + 8) * DK + c) =
                    make_float2(acc[i][j][2] + b0, acc[i][j][3] + b1);
            }
        }
    } else {   // mode 2: bf16 hi/lo split scatter (V projection)
#pragma unroll
        for (int i = 0; i < 2; i++) {
            int r0 = m0 + wm*32 + i*16 + crow;
            int b_ = r0 >> 11, t0 = r0 & (TSEQ - 1);
#pragma unroll
            for (int j = 0; j < 8; j++) {
                int n = n0 + wn*64 + j*8 + ccol;
                int h = n >> 6, c = n & 63;
                float b0 = __ldg(bias + n), b1 = __ldg(bias + n + 1);
                size_t base = ((size_t)(b_ * NH + h) * TSEQ);
                float v0 = acc[i][j][0] + b0, v1 = acc[i][j][1] + b1;
                float v2 = acc[i][j][2] + b0, v3 = acc[i][j][3] + b1;
                __nv_bfloat16 h0, h1, h2, h3, l0, l1, l2, l3;
                split1(v0, h0, l0); split1(v1, h1, l1);
                split1(v2, h2, l2); split1(v3, h3, l3);
                *(__nv_bfloat162*)(outh + (base + t0) * DK + c)     = __halves2bfloat162(h0, h1);
                *(__nv_bfloat162*)(outl + (base + t0) * DK + c)     = __halves2bfloat162(l0, l1);
                *(__nv_bfloat162*)(outh + (base + t0 + 8) * DK + c) = __halves2bfloat162(h2, h3);
                *(__nv_bfloat162*)(outl + (base + t0 + 8) * DK + c) = __halves2bfloat162(l2, l3);
            }
        }
    }
}

// =========================================================================
// RoPE + split: reads fp32 g_Q/g_K, writes bf16 hi/lo (Q pre-scaled 1/8)
// =========================================================================
__global__ void rope_split_kernel()
{
    int idx = blockIdx.x * blockDim.x + threadIdx.x;
    int i  = idx & 31;
    int t  = (idx >> 5) & (TSEQ - 1);
    int bh = idx >> 16;

    float invf = exp2f(-(float)i * (0.031250f * 13.287712379549449f));
    float ang  = (float)t * invf;
    float s, c;
    sincosf(ang, &s, &c);

    int base = (bh * TSEQ + t) * DK + i;
    float q1 = g_Q[base], q2 = g_Q[base + 32];
    float qa = (q1 * c - q2 * s) * 0.125f;
    float qb = (q2 * c + q1 * s) * 0.125f;
    float k1 = g_K[base], k2 = g_K[base + 32];
    float ka = k1 * c - k2 * s;
    float kb = k2 * c + k1 * s;

    __nv_bfloat16 h, l;
    split1(qa, h, l); g_Qh[base]      = h; g_Ql[base]      = l;
    split1(qb, h, l); g_Qh[base + 32] = h; g_Ql[base + 32] = l;
    split1(ka, h, l); g_Kh[base]      = h; g_Kl[base]      = l;
    split1(kb, h, l); g_Kh[base + 32] = h; g_Kl[base + 32] = l;
}

// =========================================================================
// HMMA flash attention. CTA = 128 queries x 8 warps (16 q-rows each).
// K-tile 64, double-buffered cp.async K/V (hi+lo).
// S = Qh Kh + Qh Kl + Ql Kh; online softmax; P split in registers;
// O += Ph Vh + Ph Vl + Pl Vh. Output written pre-split to g_Ahi/g_Alo.
// =========================================================================
#define A2_QH   0
#define A2_QL   16384
#define A2_STG  32768
#define A2_STGS 32768     // per stage: KH 8K | KL 8K | VH 8K | VL 8K
#define A2_MASK 98304
#define A2_SMEM (A2_MASK + TSEQ*4)   // 106496

__global__ __launch_bounds__(256, 1)
void attn_hmma(const unsigned char* __restrict__ mask)
{
    extern __shared__ char smem[];
    uint32_t sb = smem_u32(smem);
    int tid = threadIdx.x, lane = tid & 31, wid = tid >> 5;
    int bh = blockIdx.y, b = bh >> 4, h = bh & 15;
    int q0 = blockIdx.x * 128;
    int rlane = lane & 15, kc = lane >> 4;

    // ---- Q tiles (group 0) ----
    {
        size_t qb = ((size_t)bh * TSEQ + q0) * DK;
#pragma unroll
        for (int i = 0; i < 4; i++) {
            int seg = tid + i * 256;
            int r = seg >> 3, c = seg & 7;
            uint32_t sw = SW128((uint32_t)(r * 128 + c * 16));
            size_t go = qb + (size_t)r * DK + c * 8;
            cp_async16(sb + A2_QH + sw, g_Qh + go);
            cp_async16(sb + A2_QL + sw, g_Ql + go);
        }
        cp_commit();
    }
    auto load_stage = [&](int s, int kt) {
        uint32_t st = sb + A2_STG + s * A2_STGS;
        size_t base = ((size_t)bh * TSEQ + kt * 64) * DK;
#pragma unroll
        for (int i = 0; i < 2; i++) {
            int seg = tid + i * 256;
            int r = seg >> 3, c = seg & 7;
            uint32_t sw = SW128((uint32_t)(r * 128 + c * 16));
            size_t go = base + (size_t)r * DK + c * 8;
            cp_async16(st + sw,         g_Kh + go);
            cp_async16(st + 8192 + sw,  g_Kl + go);
            cp_async16(st + 16384 + sw, g_Vh + go);
            cp_async16(st + 24576 + sw, g_Vl + go);
        }
        cp_commit();
    };
    load_stage(0, 0);

    {   // mask -> additive fp32 bias row
        const unsigned char* mkp = mask + (size_t)b * TSEQ;
        float* msk = (float*)(smem + A2_MASK);
#pragma unroll
        for (int i = 0; i < 8; i++) {
            int t = tid * 8 + i;
            msk[t] = mkp[t] ? -1e30f : 0.f;
        }
    }

    cp_wait<1>();          // Q group done
    __syncthreads();

    // ---- Q fragments held in registers for the whole kernel ----
    uint32_t aqh[4][4], aql[4][4];
#pragma unroll
    for (int ks = 0; ks < 4; ks++) {
        uint32_t off = SW128((uint32_t)((wid*16 + rlane) * 128 + (ks*2 + kc) * 16));
        ldm_x4(aqh[ks], sb + A2_QH + off);
        ldm_x4(aql[ks], sb + A2_QL + off);
    }

    float m0 = -1e30f, m1 = -1e30f, l0 = 0.f, l1 = 0.f;
    float o[8][4];
#pragma unroll
    for (int j = 0; j < 8; j++)
#pragma unroll
        for (int r = 0; r < 4; r++) o[j][r] = 0.f;

    const float* msk = (const float*)(smem + A2_MASK);

    for (int kt = 0; kt < 32; kt++) {
        int s = kt & 1;
        __syncthreads();                     // stage s^1 free for overwrite
        if (kt + 1 < 32) { load_stage(s ^ 1, kt + 1); cp_wait<1>(); }
        else             { cp_wait<0>(); }
        __syncthreads();

        uint32_t stKh = sb + A2_STG + s * A2_STGS;
        uint32_t stKl = stKh + 8192;
        uint32_t stVh = stKh + 16384;
        uint32_t stVl = stKh + 24576;

        // ---- S = Q K^T (bf16x3) ----
        float sv[8][4];
#pragma unroll
        for (int j = 0; j < 8; j++)
#pragma unroll
            for (int r = 0; r < 4; r++) sv[j][r] = 0.f;

#pragma unroll
        for (int ks = 0; ks < 4; ks++) {
            int koff = (ks*2 + kc) * 16;
            uint32_t bkh[8][2], bkl[8][2];
#pragma unroll
            for (int jj = 0; jj < 4; jj++) {
                uint32_t off = SW128((uint32_t)((jj*16 + rlane) * 128 + koff));
                uint32_t r[4];
                ldm_x4(r, stKh + off);
                bkh[2*jj][0] = r[0]; bkh[2*jj+1][0] = r[1];
                bkh[2*jj][1] = r[2]; bkh[2*jj+1][1] = r[3];
                ldm_x4(r, stKl + off);
                bkl[2*jj][0] = r[0]; bkl[2*jj+1][0] = r[1];
                bkl[2*jj][1] = r[2]; bkl[2*jj+1][1] = r[3];
            }
#pragma unroll
            for (int j = 0; j < 8; j++) {
                mma16816(sv[j], aqh[ks], bkh[j][0], bkh[j][1]);
                mma16816(sv[j], aqh[ks], bkl[j][0], bkl[j][1]);
                mma16816(sv[j], aql[ks], bkh[j][0], bkh[j][1]);
            }
        }

        // ---- mask + online softmax ----
        int mbase = kt * 64 + (lane & 3) * 2;
#pragma unroll
        for (int j = 0; j < 8; j++) {
            float mb0 = msk[mbase + j*8], mb1 = msk[mbase + j*8 + 1];
            sv[j][0] += mb0; sv[j][1] += mb1;
            sv[j][2] += mb0; sv[j][3] += mb1;
        }
        float mx0 = -1e30f, mx1 = -1e30f;
#pragma unroll
        for (int j = 0; j < 8; j++) {
            mx0 = fmaxf(mx0, fmaxf(sv[j][0], sv[j][1]));
            mx1 = fmaxf(mx1, fmaxf(sv[j][2], sv[j][3]));
        }
        mx0 = fmaxf(mx0, __shfl_xor_sync(0xffffffffu, mx0, 1));
        mx0 = fmaxf(mx0, __shfl_xor_sync(0xffffffffu, mx0, 2));
        mx1 = fmaxf(mx1, __shfl_xor_sync(0xffffffffu, mx1, 1));
        mx1 = fmaxf(mx1, __shfl_xor_sync(0xffffffffu, mx1, 2));
        float mn0 = fmaxf(m0, mx0), mn1 = fmaxf(m1, mx1);
        float al0 = __expf(m0 - mn0), al1 = __expf(m1 - mn1);
        m0 = mn0; m1 = mn1;

        float ls0 = 0.f, ls1 = 0.f;
        uint32_t pha[8], phb[8], pla[8], plb[8];
#pragma unroll
        for (int j = 0; j < 8; j++) {
            float p0 = __expf(sv[j][0] - mn0);
            float p1 = __expf(sv[j][1] - mn0);
            float p2 = __expf(sv[j][2] - mn1);
            float p3 = __expf(sv[j][3] - mn1);
            ls0 += p0 + p1;  ls1 += p2 + p3;
            pha[j] = packbf(p0, p1);
            phb[j] = packbf(p2, p3);
            pla[j] = packbf(p0 - __uint_as_float(pha[j] << 16),
                            p1 - __uint_as_float(pha[j] & 0xFFFF0000u));
            plb[j] = packbf(p2 - __uint_as_float(phb[j] << 16),
                            p3 - __uint_as_float(phb[j] & 0xFFFF0000u));
        }
        l0 = l0 * al0 + ls0;
        l1 = l1 * al1 + ls1;
#pragma unroll
        for (int j = 0; j < 8; j++) {
            o[j][0] *= al0; o[j][1] *= al0;
            o[j][2] *= al1; o[j][3] *= al1;
        }

        // ---- O += P V (bf16x3, V via trans ldmatrix) ----
#pragma unroll
        for (int ks = 0; ks < 4; ks++) {
            uint32_t pa_h[4] = {pha[2*ks], phb[2*ks], pha[2*ks+1], phb[2*ks+1]};
            uint32_t pa_l[4] = {pla[2*ks], plb[2*ks], pla[2*ks+1], plb[2*ks+1]};
            uint32_t bvh[8][2], bvl[8][2];
#pragma unroll
            for (int jj = 0; jj < 4; jj++) {
                uint32_t off = SW128((uint32_t)((ks*16 + rlane) * 128 + (jj*2 + kc) * 16));
                uint32_t r[4];
                ldm_x4_t(r, stVh + off);
                bvh[2*jj][0] = r[0]; bvh[2*jj][1] = r[1];
                bvh[2*jj+1][0] = r[2]; bvh[2*jj+1][1] = r[3];
                ldm_x4_t(r, stVl + off);
                bvl[2*jj][0] = r[0]; bvl[2*jj][1] = r[1];
                bvl[2*jj+1][0] = r[2]; bvl[2*jj+1][1] = r[3];
            }
#pragma unroll
            for (int j = 0; j < 8; j++) {
                mma16816(o[j], pa_h, bvh[j][0], bvh[j][1]);
                mma16816(o[j], pa_h, bvl[j][0], bvl[j][1]);
                mma16816(o[j], pa_l, bvh[j][0], bvh[j][1]);
            }
        }
    }

    // ---- finalize: normalize by l, write pre-split bf16 to g_Ahi/g_Alo ----
    l0 += __shfl_xor_sync(0xffffffffu, l0, 1);
    l0 += __shfl_xor_sync(0xffffffffu, l0, 2);
    l1 += __shfl_xor_sync(0xffffffffu, l1, 1);
    l1 += __shfl_xor_sync(0xffffffffu, l1, 2);
    float inv0 = 1.f / l0, inv1 = 1.f / l1;

    int row0 = q0 + wid * 16 + (lane >> 2);
    int colb = h * DK + (lane & 3) * 2;
#pragma unroll
    for (int j = 0; j < 8; j++) {
        int col = colb + j * 8;
        float v0 = o[j][0] * inv0, v1 = o[j][1] * inv0;
        float v2 = o[j][2] * inv1, v3 = o[j][3] * inv1;
        __nv_bfloat16 h0, h1, h2, h3, q0b, q1b, q2b, q3b;
        split1(v0, h0, q0b); split1(v1, h1, q1b);
        split1(v2, h2, q2b); split1(v3, h3, q3b);
        size_t i0 = ((size_t)(b * TSEQ + row0)) * DMODEL + col;
        size_t i1 = ((size_t)(b * TSEQ + row0 + 8)) * DMODEL + col;
        *(__nv_bfloat162*)&g_Ahi[i0] = __halves2bfloat162(h0, h1);
        *(__nv_bfloat162*)&g_Alo[i0] = __halves2bfloat162(q0b, q1b);
        *(__nv_bfloat162*)&g_Ahi[i1] = __halves2bfloat162(h2, h3);
        *(__nv_bfloat162*)&g_Alo[i1] = __halves2bfloat162(q2b, q3b);
    }
}

// =========================================================================
// launch
// =========================================================================
extern "C" void kernel_launch(void* const* d_in, const int* in_sizes, int n_in,
                              void* d_out, int out_size)
{
    const float* x          = (const float*)d_in[0];
    const unsigned char* mk = (const unsigned char*)d_in[1];
    const float* Wq = (const float*)d_in[2];
    const float* bq = (const float*)d_in[3];
    const float* Wk = (const float*)d_in[4];
    const float* bk = (const float*)d_in[5];
    const float* Wv = (const float*)d_in[6];
    const float* bv = (const float*)d_in[7];
    const float* Wo = (const float*)d_in[8];
    const float* bo = (const float*)d_in[9];
    float* out = (float*)d_out;

    float *qp, *kp;
    __nv_bfloat16 *ah, *al, *vh, *vl;
    __nv_bfloat16 *wqh, *wql, *wkh, *wkl, *wvh, *wvl, *woh, *wol;
    cudaGetSymbolAddress((void**)&qp, g_Q);
    cudaGetSymbolAddress((void**)&kp, g_K);
    cudaGetSymbolAddress((void**)&ah, g_Ahi);
    cudaGetSymbolAddress((void**)&al, g_Alo);
    cudaGetSymbolAddress((void**)&vh, g_Vh);
    cudaGetSymbolAddress((void**)&vl, g_Vl);
    cudaGetSymbolAddress((void**)&wqh, g_Wqh);  cudaGetSymbolAddress((void**)&wql, g_Wql);
    cudaGetSymbolAddress((void**)&wkh, g_Wkh);  cudaGetSymbolAddress((void**)&wkl, g_Wkl);
    cudaGetSymbolAddress((void**)&wvh, g_Wvh);  cudaGetSymbolAddress((void**)&wvl, g_Wvl);
    cudaGetSymbolAddress((void**)&woh, g_Woh);  cudaGetSymbolAddress((void**)&wol, g_Wol);

    cudaFuncSetAttribute(gemm_hmma, cudaFuncAttributeMaxDynamicSharedMemorySize, GEMM_SMEM);
    cudaFuncSetAttribute(attn_hmma, cudaFuncAttributeMaxDynamicSharedMemorySize, A2_SMEM);

    const int NW = DMODEL * DMODEL;   // 1048576
    const int NX = MROWS * DMODEL;    // 8388608

    split_kernel<<<NX / 1024, 256>>>(x, ah, al, NX);
    split_kernel<<<NW / 1024, 256>>>(Wq, wqh, wql, NW);
    split_kernel<<<NW / 1024, 256>>>(Wk, wkh, wkl, NW);
    split_kernel<<<NW / 1024, 256>>>(Wv, wvh, wvl, NW);
    split_kernel<<<NW / 1024, 256>>>(Wo, woh, wol, NW);

    dim3 gg(DMODEL / 128, MROWS / 128);   // (8, 64)
    gemm_hmma<<<gg, 256, GEMM_SMEM>>>(ah, al, wqh, wql, bq, qp, 0, 0, 1);
    gemm_hmma<<<gg, 256, GEMM_SMEM>>>(ah, al, wkh, wkl, bk, kp, 0, 0, 1);
    gemm_hmma<<<gg, 256, GEMM_SMEM>>>(ah, al, wvh, wvl, bv, 0, vh, vl, 2);

    rope_split_kernel<<<(BSZ * NH * TSEQ * 32) / 256, 256>>>();

    dim3 ag(TSEQ / 128, BSZ * NH);        // (16, 64)
    attn_hmma<<<ag, 256, A2_SMEM>>>(mk);  // writes pre-split g_Ahi/g_Alo

    gemm_hmma<<<gg, 256, GEMM_SMEM>>>(ah, al, woh, wol, bo, out, 0, 0, 0);
}

// round 7
// speedup vs baseline: 3.2010x; 1.0356x over previous
#include <cuda_runtime.h>
#include <cuda_bf16.h>
#include <math.h>
#include <stdint.h>

// ---------------- problem constants ----------------
#define BSZ    4
#define TSEQ   2048
#define DMODEL 1024
#define NH     16
#define DK     64
#define MROWS  (BSZ*TSEQ)          // 8192
#define QKV_ELEMS (BSZ*NH*TSEQ*DK) // 8388608

// ---------------- scratch (static device globals) ----------------
__device__ float g_Q[QKV_ELEMS];
__device__ float g_K[QKV_ELEMS];
__device__ __nv_bfloat16 g_Ahi[MROWS*DMODEL];
__device__ __nv_bfloat16 g_Alo[MROWS*DMODEL];
__device__ __nv_bfloat16 g_Qh[QKV_ELEMS], g_Ql[QKV_ELEMS];
__device__ __nv_bfloat16 g_Kh[QKV_ELEMS], g_Kl[QKV_ELEMS];
__device__ __nv_bfloat16 g_Vh[QKV_ELEMS], g_Vl[QKV_ELEMS];
__device__ __nv_bfloat16 g_Wqh[DMODEL*DMODEL], g_Wql[DMODEL*DMODEL];
__device__ __nv_bfloat16 g_Wkh[DMODEL*DMODEL], g_Wkl[DMODEL*DMODEL];
__device__ __nv_bfloat16 g_Wvh[DMODEL*DMODEL], g_Wvl[DMODEL*DMODEL];
__device__ __nv_bfloat16 g_Woh[DMODEL*DMODEL], g_Wol[DMODEL*DMODEL];

// =========================================================================
// PTX helpers (sm_100 baseline: cp.async, ldmatrix, mma.sync)
// =========================================================================
__device__ __forceinline__ uint32_t smem_u32(const void* p) {
    uint32_t a;
    asm("{ .reg .u64 t; cvta.to.shared.u64 t, %1; cvt.u32.u64 %0, t; }"
        : "=r"(a) : "l"(p));
    return a;
}
#define SW128(off) ((off) ^ (((off) >> 3) & 0x70))

__device__ __forceinline__ void cp_async16(uint32_t s, const void* g) {
    asm volatile("cp.async.cg.shared.global [%0], [%1], 16;" :: "r"(s), "l"(g));
}
__device__ __forceinline__ void cp_commit() {
    asm volatile("cp.async.commit_group;" ::: "memory");
}
template <int N> __device__ __forceinline__ void cp_wait() {
    asm volatile("cp.async.wait_group %0;" :: "n"(N) : "memory");
}

__device__ __forceinline__ void ldm_x4(uint32_t* r, uint32_t addr) {
    asm volatile("ldmatrix.sync.aligned.m8n8.x4.shared.b16 {%0,%1,%2,%3}, [%4];"
        : "=r"(r[0]), "=r"(r[1]), "=r"(r[2]), "=r"(r[3]) : "r"(addr));
}
__device__ __forceinline__ void ldm_x4_t(uint32_t* r, uint32_t addr) {
    asm volatile("ldmatrix.sync.aligned.m8n8.x4.trans.shared.b16 {%0,%1,%2,%3}, [%4];"
        : "=r"(r[0]), "=r"(r[1]), "=r"(r[2]), "=r"(r[3]) : "r"(addr));
}

__device__ __forceinline__ void mma16816(float* c, const uint32_t* a,
                                         uint32_t b0, uint32_t b1) {
    asm volatile(
        "mma.sync.aligned.m16n8k16.row.col.f32.bf16.bf16.f32 "
        "{%0,%1,%2,%3}, {%4,%5,%6,%7}, {%8,%9}, {%0,%1,%2,%3};"
        : "+f"(c[0]), "+f"(c[1]), "+f"(c[2]), "+f"(c[3])
        : "r"(a[0]), "r"(a[1]), "r"(a[2]), "r"(a[3]), "r"(b0), "r"(b1));
}

// pack two fp32 into bf16x2 (first arg in low half)
__device__ __forceinline__ uint32_t packbf(float lo, float hi) {
    uint32_t r;
    asm("cvt.rn.bf16x2.f32 %0, %1, %2;" : "=r"(r) : "f"(hi), "f"(lo));
    return r;
}

// split one fp32 into bf16 hi + bf16 lo
__device__ __forceinline__ void split1(float v, __nv_bfloat16& h, __nv_bfloat16& l) {
    h = __float2bfloat16(v);
    l = __float2bfloat16(v - __bfloat162float(h));
}

// =========================================================================
// fp32 -> (bf16 hi, bf16 lo) split
// =========================================================================
__global__ void split_kernel(const float* __restrict__ src,
                             __nv_bfloat16* __restrict__ hi,
                             __nv_bfloat16* __restrict__ lo, int n)
{
    int i = (blockIdx.x * blockDim.x + threadIdx.x) * 4;
    if (i >= n) return;
    float4 v = *(const float4*)(src + i);
    __nv_bfloat16 h0, h1, h2, h3, l0, l1, l2, l3;
    split1(v.x, h0, l0); split1(v.y, h1, l1);
    split1(v.z, h2, l2); split1(v.w, h3, l3);
    *(__nv_bfloat162*)(hi + i)     = __halves2bfloat162(h0, h1);
    *(__nv_bfloat162*)(hi + i + 2) = __halves2bfloat162(h2, h3);
    *(__nv_bfloat162*)(lo + i)     = __halves2bfloat162(l0, l1);
    *(__nv_bfloat162*)(lo + i + 2) = __halves2bfloat162(l2, l3);
}

// =========================================================================
// HMMA bf16x3 GEMM core. CTA tile 128m x 256n, K-chunk 64 double buffered.
// 8 warps in 2(m) x 4(n), warp tile 64x64.
// Stage: A_h 16K | A_l 16K | B_h 32K | B_l 32K = 96KB; 2 stages = 192KB.
// mode 1: (B,H,T,dk) fp32 scatter; mode 2: bf16 hi/lo scatter; mode 0: row-major
// =========================================================================
#define KCH 64
#define NKB (DMODEL / KCH)        // 16
#define A_TILE 16384              // 128 rows * 128B
#define B_TILE 32768              // 256 rows * 128B
#define STG_SZ (2*A_TILE + 2*B_TILE)  // 98304
#define GEMM_SMEM (2 * STG_SZ)        // 196608

struct GemmOut {
    float* out;
    __nv_bfloat16* outh;
    __nv_bfloat16* outl;
    const float* bias;
    const __nv_bfloat16* Bh;
    const __nv_bfloat16* Bl;
    int mode;
};

__device__ __forceinline__ void gemm_core(
    const __nv_bfloat16* __restrict__ Ah, const __nv_bfloat16* __restrict__ Al,
    const __nv_bfloat16* __restrict__ Bh, const __nv_bfloat16* __restrict__ Bl,
    const float* __restrict__ bias, float* __restrict__ out,
    __nv_bfloat16* __restrict__ outh, __nv_bfloat16* __restrict__ outl,
    int mode, char* smem, int m0, int n0)
{
    uint32_t sb = smem_u32(smem);
    int tid = threadIdx.x, lane = tid & 31, wid = tid >> 5;
    int wm = wid & 1, wn = wid >> 1;      // 2(m) x 4(n), warp tile 64x64

    float acc[4][8][4];
#pragma unroll
    for (int i = 0; i < 4; i++)
#pragma unroll
        for (int j = 0; j < 8; j++)
#pragma unroll
            for (int r = 0; r < 4; r++) acc[i][j][r] = 0.f;

    auto load_stage = [&](int s, int kb) {
        uint32_t st = sb + s * STG_SZ;
        const __nv_bfloat16* pa_h = Ah + (size_t)m0 * DMODEL + kb * KCH;
        const __nv_bfloat16* pa_l = Al + (size_t)m0 * DMODEL + kb * KCH;
        const __nv_bfloat16* pb_h = Bh + (size_t)n0 * DMODEL + kb * KCH;
        const __nv_bfloat16* pb_l = Bl + (size_t)n0 * DMODEL + kb * KCH;
#pragma unroll
        for (int i = 0; i < 4; i++) {           // A: 1024 segs hi+lo
            int seg = tid + i * 256;
            int r = seg >> 3, c = seg & 7;
            uint32_t sw = SW128((uint32_t)(r * 128 + c * 16));
            const size_t go = (size_t)r * DMODEL + c * 8;
            cp_async16(st + sw,           pa_h + go);
            cp_async16(st + A_TILE + sw,  pa_l + go);
        }
#pragma unroll
        for (int i = 0; i < 8; i++) {           // B: 2048 segs hi+lo
            int seg = tid + i * 256;
            int r = seg >> 3, c = seg & 7;
            uint32_t sw = SW128((uint32_t)(r * 128 + c * 16));
            const size_t go = (size_t)r * DMODEL + c * 8;
            cp_async16(st + 2*A_TILE + sw,          pb_h + go);
            cp_async16(st + 2*A_TILE + B_TILE + sw, pb_l + go);
        }
        cp_commit();
    };

    load_stage(0, 0);

    int rlane = lane & 15;
    int kc    = lane >> 4;

    for (int kb = 0; kb < NKB; kb++) {
        int s = kb & 1;
        if (kb + 1 < NKB) { load_stage(s ^ 1, kb + 1); cp_wait<1>(); }
        else              { cp_wait<0>(); }
        __syncthreads();

        uint32_t stA  = sb + s * STG_SZ;
        uint32_t stAl = stA + A_TILE;
        uint32_t stB  = stA + 2 * A_TILE;
        uint32_t stBl = stB + B_TILE;

#pragma unroll
        for (int ks = 0; ks < 4; ks++) {
            int koff = (ks * 2 + kc) * 16;
            uint32_t a_h[4][4], a_l[4][4];
#pragma unroll
            for (int i = 0; i < 4; i++) {
                uint32_t off = SW128((uint32_t)((wm*64 + i*16 + rlane) * 128 + koff));
                ldm_x4(a_h[i], stA  + off);
                ldm_x4(a_l[i], stAl + off);
            }
#pragma unroll
            for (int jj = 0; jj < 4; jj++) {    // 2 n8-tiles per jj
                uint32_t off = SW128((uint32_t)((wn*64 + jj*16 + rlane) * 128 + koff));
                uint32_t rh[4], rl[4];
                ldm_x4(rh, stB + off);
                ldm_x4(rl, stBl + off);
#pragma unroll
                for (int i = 0; i < 4; i++) {
                    mma16816(acc[i][2*jj],   a_h[i], rh[0], rh[2]);
                    mma16816(acc[i][2*jj],   a_h[i], rl[0], rl[2]);
                    mma16816(acc[i][2*jj],   a_l[i], rh[0], rh[2]);
                    mma16816(acc[i][2*jj+1], a_h[i], rh[1], rh[3]);
                    mma16816(acc[i][2*jj+1], a_h[i], rl[1], rl[3]);
                    mma16816(acc[i][2*jj+1], a_l[i], rh[1], rh[3]);
                }
            }
        }
        __syncthreads();
    }

    int crow = lane >> 2;
    int ccol = (lane & 3) * 2;
    if (mode == 0) {
#pragma unroll
        for (int i = 0; i < 4; i++) {
            int r0 = m0 + wm*64 + i*16 + crow;
#pragma unroll
            for (int j = 0; j < 8; j++) {
                int n = n0 + wn*64 + j*8 + ccol;
                float b0 = __ldg(bias + n), b1 = __ldg(bias + n + 1);
                *(float2*)(out + (size_t)r0 * DMODEL + n) =
                    make_float2(acc[i][j][0] + b0, acc[i][j][1] + b1);
                *(float2*)(out + (size_t)(r0 + 8) * DMODEL + n) =
                    make_float2(acc[i][j][2] + b0, acc[i][j][3] + b1);
            }
        }
    } else if (mode == 1) {
#pragma unroll
        for (int i = 0; i < 4; i++) {
            int r0 = m0 + wm*64 + i*16 + crow;
            int b_ = r0 >> 11, t0 = r0 & (TSEQ - 1);
#pragma unroll
            for (int j = 0; j < 8; j++) {
                int n = n0 + wn*64 + j*8 + ccol;
                int h = n >> 6, c = n & 63;
                float b0 = __ldg(bias + n), b1 = __ldg(bias + n + 1);
                size_t base = ((size_t)(b_ * NH + h) * TSEQ);
                *(float2*)(out + (base + t0) * DK + c) =
                    make_float2(acc[i][j][0] + b0, acc[i][j][1] + b1);
                *(float2*)(out + (base + t0 + 8) * DK + c) =
                    make_float2(acc[i][j][2] + b0, acc[i][j][3] + b1);
            }
        }
    } else {   // mode 2: bf16 hi/lo split scatter (V projection)
#pragma unroll
        for (int i = 0; i < 4; i++) {
            int r0 = m0 + wm*64 + i*16 + crow;
            int b_ = r0 >> 11, t0 = r0 & (TSEQ - 1);
#pragma unroll
            for (int j = 0; j < 8; j++) {
                int n = n0 + wn*64 + j*8 + ccol;
                int h = n >> 6, c = n & 63;
                float b0 = __ldg(bias + n), b1 = __ldg(bias + n + 1);
                size_t base = ((size_t)(b_ * NH + h) * TSEQ);
                float v0 = acc[i][j][0] + b0, v1 = acc[i][j][1] + b1;
                float v2 = acc[i][j][2] + b0, v3 = acc[i][j][3] + b1;
                __nv_bfloat16 h0, h1, h2, h3, l0, l1, l2, l3;
                split1(v0, h0, l0); split1(v1, h1, l1);
                split1(v2, h2, l2); split1(v3, h3, l3);
                *(__nv_bfloat162*)(outh + (base + t0) * DK + c)     = __halves2bfloat162(h0, h1);
                *(__nv_bfloat162*)(outl + (base + t0) * DK + c)     = __halves2bfloat162(l0, l1);
                *(__nv_bfloat162*)(outh + (base + t0 + 8) * DK + c) = __halves2bfloat162(h2, h3);
                *(__nv_bfloat162*)(outl + (base + t0 + 8) * DK + c) = __halves2bfloat162(l2, l3);
            }
        }
    }
}

// fused QKV: blockIdx.z selects weight/output set
__global__ __launch_bounds__(256, 1)
void gemm_qkv(const __nv_bfloat16* __restrict__ Ah, const __nv_bfloat16* __restrict__ Al,
              const __nv_bfloat16* __restrict__ wqh, const __nv_bfloat16* __restrict__ wql,
              const __nv_bfloat16* __restrict__ wkh, const __nv_bfloat16* __restrict__ wkl,
              const __nv_bfloat16* __restrict__ wvh, const __nv_bfloat16* __restrict__ wvl,
              const float* __restrict__ bq, const float* __restrict__ bk,
              const float* __restrict__ bv,
              float* __restrict__ outq, float* __restrict__ outk,
              __nv_bfloat16* __restrict__ vh, __nv_bfloat16* __restrict__ vl)
{
    extern __shared__ char smem[];
    int m0 = blockIdx.y * 128;
    int n0 = blockIdx.x * 256;
    int z = blockIdx.z;
    if (z == 0)
        gemm_core(Ah, Al, wqh, wql, bq, outq, 0, 0, 1, smem, m0, n0);
    else if (z == 1)
        gemm_core(Ah, Al, wkh, wkl, bk, outk, 0, 0, 1, smem, m0, n0);
    else
        gemm_core(Ah, Al, wvh, wvl, bv, 0, vh, vl, 2, smem, m0, n0);
}

// output projection
__global__ __launch_bounds__(256, 1)
void gemm_out(const __nv_bfloat16* __restrict__ Ah, const __nv_bfloat16* __restrict__ Al,
              const __nv_bfloat16* __restrict__ Bh, const __nv_bfloat16* __restrict__ Bl,
              const float* __restrict__ bias, float* __restrict__ out)
{
    extern __shared__ char smem[];
    gemm_core(Ah, Al, Bh, Bl, bias, out, 0, 0, 0, smem,
              blockIdx.y * 128, blockIdx.x * 256);
}

// =========================================================================
// RoPE + split: reads fp32 g_Q/g_K, writes bf16 hi/lo (Q pre-scaled 1/8)
// =========================================================================
__global__ void rope_split_kernel()
{
    int idx = blockIdx.x * blockDim.x + threadIdx.x;
    int i  = idx & 31;
    int t  = (idx >> 5) & (TSEQ - 1);
    int bh = idx >> 16;

    float invf = exp2f(-(float)i * (0.031250f * 13.287712379549449f));
    float ang  = (float)t * invf;
    float s, c;
    sincosf(ang, &s, &c);

    int base = (bh * TSEQ + t) * DK + i;
    float q1 = g_Q[base], q2 = g_Q[base + 32];
    float qa = (q1 * c - q2 * s) * 0.125f;
    float qb = (q2 * c + q1 * s) * 0.125f;
    float k1 = g_K[base], k2 = g_K[base + 32];
    float ka = k1 * c - k2 * s;
    float kb = k2 * c + k1 * s;

    __nv_bfloat16 h, l;
    split1(qa, h, l); g_Qh[base]      = h; g_Ql[base]      = l;
    split1(qb, h, l); g_Qh[base + 32] = h; g_Ql[base + 32] = l;
    split1(ka, h, l); g_Kh[base]      = h; g_Kl[base]      = l;
    split1(kb, h, l); g_Kh[base + 32] = h; g_Kl[base + 32] = l;
}

// =========================================================================
// HMMA flash attention (unchanged from R6; writes pre-split g_Ahi/g_Alo)
// =========================================================================
#define A2_QH   0
#define A2_QL   16384
#define A2_STG  32768
#define A2_STGS 32768
#define A2_MASK 98304
#define A2_SMEM (A2_MASK + TSEQ*4)   // 106496

__global__ __launch_bounds__(256, 1)
void attn_hmma(const unsigned char* __restrict__ mask)
{
    extern __shared__ char smem[];
    uint32_t sb = smem_u32(smem);
    int tid = threadIdx.x, lane = tid & 31, wid = tid >> 5;
    int bh = blockIdx.y, b = bh >> 4, h = bh & 15;
    int q0 = blockIdx.x * 128;
    int rlane = lane & 15, kc = lane >> 4;

    {
        size_t qb = ((size_t)bh * TSEQ + q0) * DK;
#pragma unroll
        for (int i = 0; i < 4; i++) {
            int seg = tid + i * 256;
            int r = seg >> 3, c = seg & 7;
            uint32_t sw = SW128((uint32_t)(r * 128 + c * 16));
            size_t go = qb + (size_t)r * DK + c * 8;
            cp_async16(sb + A2_QH + sw, g_Qh + go);
            cp_async16(sb + A2_QL + sw, g_Ql + go);
        }
        cp_commit();
    }
    auto load_stage = [&](int s, int kt) {
        uint32_t st = sb + A2_STG + s * A2_STGS;
        size_t base = ((size_t)bh * TSEQ + kt * 64) * DK;
#pragma unroll
        for (int i = 0; i < 2; i++) {
            int seg = tid + i * 256;
            int r = seg >> 3, c = seg & 7;
            uint32_t sw = SW128((uint32_t)(r * 128 + c * 16));
            size_t go = base + (size_t)r * DK + c * 8;
            cp_async16(st + sw,         g_Kh + go);
            cp_async16(st + 8192 + sw,  g_Kl + go);
            cp_async16(st + 16384 + sw, g_Vh + go);
            cp_async16(st + 24576 + sw, g_Vl + go);
        }
        cp_commit();
    };
    load_stage(0, 0);

    {
        const unsigned char* mkp = mask + (size_t)b * TSEQ;
        float* msk = (float*)(smem + A2_MASK);
#pragma unroll
        for (int i = 0; i < 8; i++) {
            int t = tid * 8 + i;
            msk[t] = mkp[t] ? -1e30f : 0.f;
        }
    }

    cp_wait<1>();
    __syncthreads();

    uint32_t aqh[4][4], aql[4][4];
#pragma unroll
    for (int ks = 0; ks < 4; ks++) {
        uint32_t off = SW128((uint32_t)((wid*16 + rlane) * 128 + (ks*2 + kc) * 16));
        ldm_x4(aqh[ks], sb + A2_QH + off);
        ldm_x4(aql[ks], sb + A2_QL + off);
    }

    float m0 = -1e30f, m1 = -1e30f, l0 = 0.f, l1 = 0.f;
    float o[8][4];
#pragma unroll
    for (int j = 0; j < 8; j++)
#pragma unroll
        for (int r = 0; r < 4; r++) o[j][r] = 0.f;

    const float* msk = (const float*)(smem + A2_MASK);

    for (int kt = 0; kt < 32; kt++) {
        int s = kt & 1;
        __syncthreads();
        if (kt + 1 < 32) { load_stage(s ^ 1, kt + 1); cp_wait<1>(); }
        else             { cp_wait<0>(); }
        __syncthreads();

        uint32_t stKh = sb + A2_STG + s * A2_STGS;
        uint32_t stKl = stKh + 8192;
        uint32_t stVh = stKh + 16384;
        uint32_t stVl = stKh + 24576;

        float sv[8][4];
#pragma unroll
        for (int j = 0; j < 8; j++)
#pragma unroll
            for (int r = 0; r < 4; r++) sv[j][r] = 0.f;

#pragma unroll
        for (int ks = 0; ks < 4; ks++) {
            int koff = (ks*2 + kc) * 16;
            uint32_t bkh[8][2], bkl[8][2];
#pragma unroll
            for (int jj = 0; jj < 4; jj++) {
                uint32_t off = SW128((uint32_t)((jj*16 + rlane) * 128 + koff));
                uint32_t r[4];
                ldm_x4(r, stKh + off);
                bkh[2*jj][0] = r[0]; bkh[2*jj+1][0] = r[1];
                bkh[2*jj][1] = r[2]; bkh[2*jj+1][1] = r[3];
                ldm_x4(r, stKl + off);
                bkl[2*jj][0] = r[0]; bkl[2*jj+1][0] = r[1];
                bkl[2*jj][1] = r[2]; bkl[2*jj+1][1] = r[3];
            }
#pragma unroll
            for (int j = 0; j < 8; j++) {
                mma16816(sv[j], aqh[ks], bkh[j][0], bkh[j][1]);
                mma16816(sv[j], aqh[ks], bkl[j][0], bkl[j][1]);
                mma16816(sv[j], aql[ks], bkh[j][0], bkh[j][1]);
            }
        }

        int mbase = kt * 64 + (lane & 3) * 2;
#pragma unroll
        for (int j = 0; j < 8; j++) {
            float mb0 = msk[mbase + j*8], mb1 = msk[mbase + j*8 + 1];
            sv[j][0] += mb0; sv[j][1] += mb1;
            sv[j][2] += mb0; sv[j][3] += mb1;
        }
        float mx0 = -1e30f, mx1 = -1e30f;
#pragma unroll
        for (int j = 0; j < 8; j++) {
            mx0 = fmaxf(mx0, fmaxf(sv[j][0], sv[j][1]));
            mx1 = fmaxf(mx1, fmaxf(sv[j][2], sv[j][3]));
        }
        mx0 = fmaxf(mx0, __shfl_xor_sync(0xffffffffu, mx0, 1));
        mx0 = fmaxf(mx0, __shfl_xor_sync(0xffffffffu, mx0, 2));
        mx1 = fmaxf(mx1, __shfl_xor_sync(0xffffffffu, mx1, 1));
        mx1 = fmaxf(mx1, __shfl_xor_sync(0xffffffffu, mx1, 2));
        float mn0 = fmaxf(m0, mx0), mn1 = fmaxf(m1, mx1);
        float al0 = __expf(m0 - mn0), al1 = __expf(m1 - mn1);
        m0 = mn0; m1 = mn1;

        float ls0 = 0.f, ls1 = 0.f;
        uint32_t pha[8], phb[8], pla[8], plb[8];
#pragma unroll
        for (int j = 0; j < 8; j++) {
            float p0 = __expf(sv[j][0] - mn0);
            float p1 = __expf(sv[j][1] - mn0);
            float p2 = __expf(sv[j][2] - mn1);
            float p3 = __expf(sv[j][3] - mn1);
            ls0 += p0 + p1;  ls1 += p2 + p3;
            pha[j] = packbf(p0, p1);
            phb[j] = packbf(p2, p3);
            pla[j] = packbf(p0 - __uint_as_float(pha[j] << 16),
                            p1 - __uint_as_float(pha[j] & 0xFFFF0000u));
            plb[j] = packbf(p2 - __uint_as_float(phb[j] << 16),
                            p3 - __uint_as_float(phb[j] & 0xFFFF0000u));
        }
        l0 = l0 * al0 + ls0;
        l1 = l1 * al1 + ls1;
#pragma unroll
        for (int j = 0; j < 8; j++) {
            o[j][0] *= al0; o[j][1] *= al0;
            o[j][2] *= al1; o[j][3] *= al1;
        }

#pragma unroll
        for (int ks = 0; ks < 4; ks++) {
            uint32_t pa_h[4] = {pha[2*ks], phb[2*ks], pha[2*ks+1], phb[2*ks+1]};
            uint32_t pa_l[4] = {pla[2*ks], plb[2*ks], pla[2*ks+1], plb[2*ks+1]};
            uint32_t bvh[8][2], bvl[8][2];
#pragma unroll
            for (int jj = 0; jj < 4; jj++) {
                uint32_t off = SW128((uint32_t)((ks*16 + rlane) * 128 + (jj*2 + kc) * 16));
                uint32_t r[4];
                ldm_x4_t(r, stVh + off);
                bvh[2*jj][0] = r[0]; bvh[2*jj][1] = r[1];
                bvh[2*jj+1][0] = r[2]; bvh[2*jj+1][1] = r[3];
                ldm_x4_t(r, stVl + off);
                bvl[2*jj][0] = r[0]; bvl[2*jj][1] = r[1];
                bvl[2*jj+1][0] = r[2]; bvl[2*jj+1][1] = r[3];
            }
#pragma unroll
            for (int j = 0; j < 8; j++) {
                mma16816(o[j], pa_h, bvh[j][0], bvh[j][1]);
                mma16816(o[j], pa_h, bvl[j][0], bvl[j][1]);
                mma16816(o[j], pa_l, bvh[j][0], bvh[j][1]);
            }
        }
    }

    l0 += __shfl_xor_sync(0xffffffffu, l0, 1);
    l0 += __shfl_xor_sync(0xffffffffu, l0, 2);
    l1 += __shfl_xor_sync(0xffffffffu, l1, 1);
    l1 += __shfl_xor_sync(0xffffffffu, l1, 2);
    float inv0 = 1.f / l0, inv1 = 1.f / l1;

    int row0 = q0 + wid * 16 + (lane >> 2);
    int colb = h * DK + (lane & 3) * 2;
#pragma unroll
    for (int j = 0; j < 8; j++) {
        int col = colb + j * 8;
        float v0 = o[j][0] * inv0, v1 = o[j][1] * inv0;
        float v2 = o[j][2] * inv1, v3 = o[j][3] * inv1;
        __nv_bfloat16 h0, h1, h2, h3, q0b, q1b, q2b, q3b;
        split1(v0, h0, q0b); split1(v1, h1, q1b);
        split1(v2, h2, q2b); split1(v3, h3, q3b);
        size_t i0 = ((size_t)(b * TSEQ + row0)) * DMODEL + col;
        size_t i1 = ((size_t)(b * TSEQ + row0 + 8)) * DMODEL + col;
        *(__nv_bfloat162*)&g_Ahi[i0] = __halves2bfloat162(h0, h1);
        *(__nv_bfloat162*)&g_Alo[i0] = __halves2bfloat162(q0b, q1b);
        *(__nv_bfloat162*)&g_Ahi[i1] = __halves2bfloat162(h2, h3);
        *(__nv_bfloat162*)&g_Alo[i1] = __halves2bfloat162(q2b, q3b);
    }
}

// =========================================================================
// launch
// =========================================================================
extern "C" void kernel_launch(void* const* d_in, const int* in_sizes, int n_in,
                              void* d_out, int out_size)
{
    const float* x          = (const float*)d_in[0];
    const unsigned char* mk = (const unsigned char*)d_in[1];
    const float* Wq = (const float*)d_in[2];
    const float* bq = (const float*)d_in[3];
    const float* Wk = (const float*)d_in[4];
    const float* bk = (const float*)d_in[5];
    const float* Wv = (const float*)d_in[6];
    const float* bv = (const float*)d_in[7];
    const float* Wo = (const float*)d_in[8];
    const float* bo = (const float*)d_in[9];
    float* out = (float*)d_out;

    float *qp, *kp;
    __nv_bfloat16 *ah, *al, *vh, *vl;
    __nv_bfloat16 *wqh, *wql, *wkh, *wkl, *wvh, *wvl, *woh, *wol;
    cudaGetSymbolAddress((void**)&qp, g_Q);
    cudaGetSymbolAddress((void**)&kp, g_K);
    cudaGetSymbolAddress((void**)&ah, g_Ahi);
    cudaGetSymbolAddress((void**)&al, g_Alo);
    cudaGetSymbolAddress((void**)&vh, g_Vh);
    cudaGetSymbolAddress((void**)&vl, g_Vl);
    cudaGetSymbolAddress((void**)&wqh, g_Wqh);  cudaGetSymbolAddress((void**)&wql, g_Wql);
    cudaGetSymbolAddress((void**)&wkh, g_Wkh);  cudaGetSymbolAddress((void**)&wkl, g_Wkl);
    cudaGetSymbolAddress((void**)&wvh, g_Wvh);  cudaGetSymbolAddress((void**)&wvl, g_Wvl);
    cudaGetSymbolAddress((void**)&woh, g_Woh);  cudaGetSymbolAddress((void**)&wol, g_Wol);

    cudaFuncSetAttribute(gemm_qkv, cudaFuncAttributeMaxDynamicSharedMemorySize, GEMM_SMEM);
    cudaFuncSetAttribute(gemm_out, cudaFuncAttributeMaxDynamicSharedMemorySize, GEMM_SMEM);
    cudaFuncSetAttribute(attn_hmma, cudaFuncAttributeMaxDynamicSharedMemorySize, A2_SMEM);

    const int NW = DMODEL * DMODEL;   // 1048576
    const int NX = MROWS * DMODEL;    // 8388608

    split_kernel<<<NX / 1024, 256>>>(x, ah, al, NX);
    split_kernel<<<NW / 1024, 256>>>(Wq, wqh, wql, NW);
    split_kernel<<<NW / 1024, 256>>>(Wk, wkh, wkl, NW);
    split_kernel<<<NW / 1024, 256>>>(Wv, wvh, wvl, NW);
    split_kernel<<<NW / 1024, 256>>>(Wo, woh, wol, NW);

    dim3 gq(DMODEL / 256, MROWS / 128, 3);   // (4, 64, 3)
    gemm_qkv<<<gq, 256, GEMM_SMEM>>>(ah, al, wqh, wql, wkh, wkl, wvh, wvl,
                                     bq, bk, bv, qp, kp, vh, vl);

    rope_split_kernel<<<(BSZ * NH * TSEQ * 32) / 256, 256>>>();

    dim3 ag(TSEQ / 128, BSZ * NH);           // (16, 64)
    attn_hmma<<<ag, 256, A2_SMEM>>>(mk);     // writes pre-split g_Ahi/g_Alo

    dim3 go(DMODEL / 256, MROWS / 128);      // (4, 64)
    gemm_out<<<go, 256, GEMM_SMEM>>>(ah, al, woh, wol, bo, out);
}